// round 5
// baseline (speedup 1.0000x reference)
#include <cuda_runtime.h>
#include <cuda_bf16.h>
#include <cuda_fp16.h>

#define N_USERS 100000
#define N_ITEMS 150000
#define NN      250000
#define NFEAT   250002
#define NNZ     4000000
#define EMB     64
#define BATCH   512

#define SCAN_T  1024
#define SCAN_B  ((NN + SCAN_T - 1) / SCAN_T)   // 245

// ---------------- scratch (device globals; no runtime allocation) ------------
__device__ int    d_cnt[NN];
__device__ int    d_rowptr[NN + 1];
__device__ int    d_pos[NN];
__device__ int    d_col[NNZ];
__device__ int    d_bsum[SCAN_B];
__device__ int    d_boff[SCAN_B];
__device__ __half d_embH[(size_t)NFEAT * EMB];
__device__ __half d_X[(size_t)4 * NN * EMB];    // pre-scaled reps x'_0..x'_3
__device__ __half d_Uh[BATCH * EMB];
__device__ __half d_Ih[(size_t)N_ITEMS * EMB];

// ---------------- emb -> fp16 ------------------------------------------------
__global__ void k_cvt_emb(const float* __restrict__ emb) {
    int i = blockIdx.x * blockDim.x + threadIdx.x;            // float4 index
    const int total = (NFEAT * EMB) / 4;
    if (i < total) {
        float4 f = ((const float4*)emb)[i];
        __half2 h0 = __floats2half2_rn(f.x, f.y);
        __half2 h1 = __floats2half2_rn(f.z, f.w);
        ((uint2*)d_embH)[i] = make_uint2(*(unsigned*)&h0, *(unsigned*)&h1);
    }
}

// ---------------- CSR build --------------------------------------------------
__global__ void k_hist(const int* __restrict__ row) {
    int i = blockIdx.x * blockDim.x + threadIdx.x;
    int stride = gridDim.x * blockDim.x;
    for (; i < NNZ / 4; i += stride) {
        int4 r = ((const int4*)row)[i];
        atomicAdd(&d_cnt[r.x], 1);
        atomicAdd(&d_cnt[r.y], 1);
        atomicAdd(&d_cnt[r.z], 1);
        atomicAdd(&d_cnt[r.w], 1);
    }
}

__device__ __forceinline__ int block_scan_incl(int v, int tid) {
    int lane = tid & 31, w = tid >> 5;
    int x = v;
    #pragma unroll
    for (int o = 1; o < 32; o <<= 1) {
        int y = __shfl_up_sync(0xffffffffu, x, o);
        if (lane >= o) x += y;
    }
    __shared__ int ws[32];
    if (lane == 31) ws[w] = x;
    __syncthreads();
    if (w == 0) {
        int y = ws[lane];
        #pragma unroll
        for (int o = 1; o < 32; o <<= 1) {
            int z = __shfl_up_sync(0xffffffffu, y, o);
            if (lane >= o) y += z;
        }
        ws[lane] = y;
    }
    __syncthreads();
    return x + (w > 0 ? ws[w - 1] : 0);
}

__global__ void k_csr1() {
    int tid = threadIdx.x;
    int i = blockIdx.x * SCAN_T + tid;
    int v = (i < NN) ? d_cnt[i] : 0;
    int incl = block_scan_incl(v, tid);
    if (tid == SCAN_T - 1) d_bsum[blockIdx.x] = incl;
}

__global__ void k_csr2() {
    int tid = threadIdx.x;
    int v = (tid < SCAN_B) ? d_bsum[tid] : 0;
    int lane = tid & 31, w = tid >> 5;
    int x = v;
    #pragma unroll
    for (int o = 1; o < 32; o <<= 1) {
        int y = __shfl_up_sync(0xffffffffu, x, o);
        if (lane >= o) x += y;
    }
    __shared__ int ws[8];
    if (lane == 31) ws[w] = x;
    __syncthreads();
    int off = 0;
    for (int j = 0; j < w; j++) off += ws[j];
    if (tid < SCAN_B) d_boff[tid] = x + off - v;
}

__global__ void k_csr3() {
    int tid = threadIdx.x;
    int i = blockIdx.x * SCAN_T + tid;
    int v = (i < NN) ? d_cnt[i] : 0;
    int incl = block_scan_incl(v, tid);
    int excl = incl - v + d_boff[blockIdx.x];
    if (i < NN) {
        d_rowptr[i] = excl;
        d_pos[i]    = excl;
        if (i == NN - 1) d_rowptr[NN] = excl + v;
    }
}

__global__ void k_scatter(const int* __restrict__ row, const int* __restrict__ col) {
    int i = blockIdx.x * blockDim.x + threadIdx.x;
    int stride = gridDim.x * blockDim.x;
    for (; i < NNZ / 4; i += stride) {
        int4 r = ((const int4*)row)[i];
        int4 c = ((const int4*)col)[i];
        int p;
        p = atomicAdd(&d_pos[r.x], 1); d_col[p] = c.x;
        p = atomicAdd(&d_pos[r.y], 1); d_col[p] = c.y;
        p = atomicAdd(&d_pos[r.z], 1); d_col[p] = c.z;
        p = atomicAdd(&d_pos[r.w], 1); d_col[p] = c.w;
    }
}

// ---- fp16 row gather helper: lane l owns 4 consecutive halves of a 64-col row
__device__ __forceinline__ float4 gather_row_h(const __half* base, int node, int l) {
    uint2 u = ((const uint2*)base)[(size_t)node * 16 + l];
    __half2 h0 = *(__half2*)&u.x;
    __half2 h1 = *(__half2*)&u.y;
    float2 f0 = __half22float2(h0);
    float2 f1 = __half22float2(h1);
    return make_float4(f0.x, f0.y, f1.x, f1.y);
}

__device__ __forceinline__ void store_row_h(__half* base, size_t idx, float4 s) {
    __half2 h0 = __floats2half2_rn(s.x, s.y);
    __half2 h1 = __floats2half2_rn(s.z, s.w);
    ((uint2*)base)[idx] = make_uint2(*(unsigned*)&h0, *(unsigned*)&h1);
}

// ---------------- layer 0: x'_0 = dinv * [rs^-0.5 * (sum embH[nbr] + embH[self]) * w]
// 16-lane groups, 2 rows per warp, 4 cols per lane; binary edges
__global__ void k_rep0(const float* __restrict__ w) {
    int lane = threadIdx.x & 31;
    int l = lane & 15;
    int sbase = lane & 16;
    int gw = (blockIdx.x * blockDim.x + threadIdx.x) >> 4;
    if (gw >= NN) return;
    int beg = d_rowptr[gw], end = d_rowptr[gw + 1];
    int len = end - beg;
    int olen = __shfl_xor_sync(0xffffffffu, len, 16);
    int maxlen = max(len, olen);

    int self = NN + (gw >= N_USERS ? 1 : 0);
    float4 s = gather_row_h(d_embH, self, l);

    for (int r0 = 0; r0 < maxlen; r0 += 16) {
        int jj = beg + r0 + l;
        int c = (jj < end) ? d_col[jj] : 0;
        int kmax = min(16, maxlen - r0);
        int klim = len - r0;                      // uniform per 16-lane half
        #pragma unroll 4
        for (int k = 0; k < kmax; k++) {
            int cc = __shfl_sync(0xffffffffu, c, sbase + k);
            if (k < klim) {
                float4 x = gather_row_h(d_embH, cc, l);
                s.x += x.x; s.y += x.y; s.z += x.z; s.w += x.w;
            }
        }
    }
    float fv = rsqrtf((float)(len + 1));
    float dinv = (len > 0) ? rsqrtf((float)len) : 1.f;
    float4 w4 = ((const float4*)w)[l];
    float g = fv * dinv;
    s.x *= g * w4.x; s.y *= g * w4.y; s.z *= g * w4.z; s.w *= g * w4.w;
    store_row_h(d_X, (size_t)gw * 16 + l, s);
}

// ---------------- adj SpMM layer: x'_l = dinv^2 * sum x'_{l-1}[nbr] ----------
__global__ void k_spmm(int layer) {
    const __half* in  = d_X + (size_t)(layer - 1) * NN * EMB;
    __half*       out = d_X + (size_t)layer * NN * EMB;
    int lane = threadIdx.x & 31;
    int l = lane & 15;
    int sbase = lane & 16;
    int gw = (blockIdx.x * blockDim.x + threadIdx.x) >> 4;
    if (gw >= NN) return;
    int beg = d_rowptr[gw], end = d_rowptr[gw + 1];
    int len = end - beg;
    int olen = __shfl_xor_sync(0xffffffffu, len, 16);
    int maxlen = max(len, olen);

    float4 s = make_float4(0.f, 0.f, 0.f, 0.f);
    for (int r0 = 0; r0 < maxlen; r0 += 16) {
        int jj = beg + r0 + l;
        int c = (jj < end) ? d_col[jj] : 0;
        int kmax = min(16, maxlen - r0);
        int klim = len - r0;
        #pragma unroll 4
        for (int k = 0; k < kmax; k++) {
            int cc = __shfl_sync(0xffffffffu, c, sbase + k);
            if (k < klim) {
                float4 x = gather_row_h(in, cc, l);
                s.x += x.x; s.y += x.y; s.z += x.z; s.w += x.w;
            }
        }
    }
    float di2 = (len > 0) ? (1.f / (float)len) : 1.f;   // dinv^2
    s.x *= di2; s.y *= di2; s.z *= di2; s.w *= di2;
    store_row_h(out, (size_t)gw * 16 + l, s);
}

// ---------------- combine: acc = 0.25 * sqrt(deg) * sum_l x'_l ---------------
// items -> d_Ih (fp16)
__global__ void k_combine_items() {
    int t = blockIdx.x * blockDim.x + threadIdx.x;
    if (t >= N_ITEMS * 16) return;
    int it = t >> 4, l = t & 15;
    int node = N_USERS + it;
    size_t idx = (size_t)node * 16 + l;
    float4 s = make_float4(0.f, 0.f, 0.f, 0.f);
    #pragma unroll
    for (int lay = 0; lay < 4; lay++) {
        float4 x = gather_row_h(d_X + (size_t)lay * NN * EMB, node, l);
        s.x += x.x; s.y += x.y; s.z += x.z; s.w += x.w;
    }
    int len = d_rowptr[node + 1] - d_rowptr[node];
    float m = ((len > 0) ? sqrtf((float)len) : 1.f) * 0.25f;
    s.x *= m; s.y *= m; s.z *= m; s.w *= m;
    store_row_h(d_Ih, (size_t)it * 16 + l, s);
}

// users -> d_Uh (fp16), only the 512 batch rows
__global__ void k_gatherU(const int* __restrict__ users) {
    int t = blockIdx.x * blockDim.x + threadIdx.x;
    if (t >= BATCH * 16) return;
    int b = t >> 4, l = t & 15;
    int node = users[b];
    float4 s = make_float4(0.f, 0.f, 0.f, 0.f);
    #pragma unroll
    for (int lay = 0; lay < 4; lay++) {
        float4 x = gather_row_h(d_X + (size_t)lay * NN * EMB, node, l);
        s.x += x.x; s.y += x.y; s.z += x.z; s.w += x.w;
    }
    int len = d_rowptr[node + 1] - d_rowptr[node];
    float m = ((len > 0) ? sqrtf((float)len) : 1.f) * 0.25f;
    s.x *= m; s.y *= m; s.z *= m; s.w *= m;
    store_row_h(d_Uh, (size_t)b * 16 + l, s);
}

// ---------------- tensor-core GEMM: out[512][150000] = Uh * Ih^T --------------
__device__ __forceinline__ unsigned smem_u32(const void* p) {
    return (unsigned)__cvta_generic_to_shared(p);
}

__global__ __launch_bounds__(256) void k_gemm_tc(float* __restrict__ out) {
    __shared__ __half Us[64][72];    // [m][k], pad 72 halves = 144B stride
    __shared__ __half Is[128][72];   // [n][k]
    int tid = threadIdx.x;
    int wid = tid >> 5, lane = tid & 31;
    int it0 = blockIdx.x * 128;
    int u0  = blockIdx.y * 64;

    for (int i = tid; i < 64 * 8; i += 256) {
        int r = i >> 3, c = i & 7;
        *(uint4*)&Us[r][c * 8] = ((const uint4*)d_Uh)[(u0 + r) * 8 + c];
    }
    for (int i = tid; i < 128 * 8; i += 256) {
        int r = i >> 3, c = i & 7;
        int git = it0 + r;
        uint4 v = make_uint4(0u, 0u, 0u, 0u);
        if (git < N_ITEMS) v = ((const uint4*)d_Ih)[(size_t)git * 8 + c];
        *(uint4*)&Is[r][c * 8] = v;
    }
    __syncthreads();

    int wm = (wid & 3) * 16;
    int wn = (wid >> 2) * 64;

    float acc[8][4];
    #pragma unroll
    for (int n = 0; n < 8; n++)
        #pragma unroll
        for (int j = 0; j < 4; j++) acc[n][j] = 0.f;

    #pragma unroll
    for (int ks = 0; ks < 4; ks++) {
        int k0 = ks * 16;
        unsigned a0, a1, a2, a3;
        {
            const __half* ap = (lane < 16) ? &Us[wm + lane][k0]
                                           : &Us[wm + lane - 16][k0 + 8];
            unsigned addr = smem_u32(ap);
            asm volatile("ldmatrix.sync.aligned.m8n8.x4.shared.b16 {%0,%1,%2,%3}, [%4];"
                         : "=r"(a0), "=r"(a1), "=r"(a2), "=r"(a3) : "r"(addr));
        }
        #pragma unroll
        for (int nt = 0; nt < 8; nt += 2) {
            unsigned b0, b1, b2, b3;
            int sub = lane >> 3;
            int rr  = wn + nt * 8 + (lane & 7) + ((sub >> 1) * 8);
            int kk  = k0 + (sub & 1) * 8;
            unsigned addr = smem_u32(&Is[rr][kk]);
            asm volatile("ldmatrix.sync.aligned.m8n8.x4.shared.b16 {%0,%1,%2,%3}, [%4];"
                         : "=r"(b0), "=r"(b1), "=r"(b2), "=r"(b3) : "r"(addr));
            asm volatile("mma.sync.aligned.m16n8k16.row.col.f32.f16.f16.f32 "
                         "{%0,%1,%2,%3}, {%4,%5,%6,%7}, {%8,%9}, {%0,%1,%2,%3};"
                         : "+f"(acc[nt][0]), "+f"(acc[nt][1]), "+f"(acc[nt][2]), "+f"(acc[nt][3])
                         : "r"(a0), "r"(a1), "r"(a2), "r"(a3), "r"(b0), "r"(b1));
            asm volatile("mma.sync.aligned.m16n8k16.row.col.f32.f16.f16.f32 "
                         "{%0,%1,%2,%3}, {%4,%5,%6,%7}, {%8,%9}, {%0,%1,%2,%3};"
                         : "+f"(acc[nt+1][0]), "+f"(acc[nt+1][1]), "+f"(acc[nt+1][2]), "+f"(acc[nt+1][3])
                         : "r"(a0), "r"(a1), "r"(a2), "r"(a3), "r"(b2), "r"(b3));
        }
    }

    int m0 = u0 + wm + (lane >> 2);
    int cbase = it0 + wn + (lane & 3) * 2;
    #pragma unroll
    for (int nt = 0; nt < 8; nt++) {
        int col = cbase + nt * 8;
        if (col < N_ITEMS) {
            *(float2*)&out[(size_t)m0 * N_ITEMS + col]       = make_float2(acc[nt][0], acc[nt][1]);
            *(float2*)&out[(size_t)(m0 + 8) * N_ITEMS + col] = make_float2(acc[nt][2], acc[nt][3]);
        }
    }
}

// ---------------- launch -----------------------------------------------------
extern "C" void kernel_launch(void* const* d_in, const int* in_sizes, int n_in,
                              void* d_out, int out_size) {
    const int*   users = (const int*)  d_in[0];
    const float* emb   = (const float*)d_in[1];
    const float* w     = (const float*)d_in[2];
    const int*   arow  = (const int*)  d_in[3];
    const int*   acol  = (const int*)  d_in[4];
    float* out = (float*)d_out;

    void* cntp = nullptr;
    cudaGetSymbolAddress(&cntp, d_cnt);
    cudaMemsetAsync(cntp, 0, NN * sizeof(int));

    k_cvt_emb<<<(NFEAT * EMB / 4 + 255) / 256, 256>>>(emb);
    k_hist<<<2048, 256>>>(arow);
    k_csr1<<<SCAN_B, SCAN_T>>>();
    k_csr2<<<1, 256>>>();
    k_csr3<<<SCAN_B, SCAN_T>>>();
    k_scatter<<<2048, 256>>>(arow, acol);

    int blocks = (NN * 16 + 255) / 256;    // 16 lanes per row
    k_rep0<<<blocks, 256>>>(w);
    k_spmm<<<blocks, 256>>>(1);
    k_spmm<<<blocks, 256>>>(2);
    k_spmm<<<blocks, 256>>>(3);

    k_combine_items<<<(N_ITEMS * 16 + 255) / 256, 256>>>();
    k_gatherU<<<(BATCH * 16 + 255) / 256, 256>>>(users);

    dim3 g((N_ITEMS + 127) / 128, BATCH / 64);
    k_gemm_tc<<<g, 256>>>(out);
}

// round 6
// speedup vs baseline: 1.4095x; 1.4095x over previous
#include <cuda_runtime.h>
#include <cuda_bf16.h>
#include <cuda_fp16.h>

#define N_USERS 100000
#define N_ITEMS 150000
#define NN      250000
#define NFEAT   250002
#define NNZ     4000000
#define EMB     64
#define BATCH   512

#define SCAN_T  1024
#define SCAN_B  ((NN + SCAN_T - 1) / SCAN_T)   // 245

// ---------------- scratch (device globals; no runtime allocation) ------------
__device__ int    d_cnt[NN];
__device__ int    d_rowptr[NN + 1];
__device__ int    d_pos[NN];
__device__ int    d_col[NNZ];
__device__ int    d_bsum[SCAN_B];
__device__ int    d_boff[SCAN_B];
__device__ __half d_embH[(size_t)NFEAT * EMB];
__device__ __half d_X[(size_t)4 * NN * EMB];    // pre-scaled reps x'_0..x'_3
__device__ __half d_Uh[BATCH * EMB];
__device__ __half d_Ih[(size_t)N_ITEMS * EMB];

// ---------------- emb -> fp16 ------------------------------------------------
__global__ void k_cvt_emb(const float* __restrict__ emb) {
    int i = blockIdx.x * blockDim.x + threadIdx.x;            // float4 index
    const int total = (NFEAT * EMB) / 4;
    if (i < total) {
        float4 f = ((const float4*)emb)[i];
        __half2 h0 = __floats2half2_rn(f.x, f.y);
        __half2 h1 = __floats2half2_rn(f.z, f.w);
        ((uint2*)d_embH)[i] = make_uint2(*(unsigned*)&h0, *(unsigned*)&h1);
    }
}

// ---------------- CSR build --------------------------------------------------
__global__ void k_hist(const int* __restrict__ row) {
    int i = blockIdx.x * blockDim.x + threadIdx.x;
    int stride = gridDim.x * blockDim.x;
    for (; i < NNZ / 4; i += stride) {
        int4 r = ((const int4*)row)[i];
        atomicAdd(&d_cnt[r.x], 1);
        atomicAdd(&d_cnt[r.y], 1);
        atomicAdd(&d_cnt[r.z], 1);
        atomicAdd(&d_cnt[r.w], 1);
    }
}

__device__ __forceinline__ int block_scan_incl(int v, int tid) {
    int lane = tid & 31, w = tid >> 5;
    int x = v;
    #pragma unroll
    for (int o = 1; o < 32; o <<= 1) {
        int y = __shfl_up_sync(0xffffffffu, x, o);
        if (lane >= o) x += y;
    }
    __shared__ int ws[32];
    if (lane == 31) ws[w] = x;
    __syncthreads();
    if (w == 0) {
        int y = ws[lane];
        #pragma unroll
        for (int o = 1; o < 32; o <<= 1) {
            int z = __shfl_up_sync(0xffffffffu, y, o);
            if (lane >= o) y += z;
        }
        ws[lane] = y;
    }
    __syncthreads();
    return x + (w > 0 ? ws[w - 1] : 0);
}

__global__ void k_csr1() {
    int tid = threadIdx.x;
    int i = blockIdx.x * SCAN_T + tid;
    int v = (i < NN) ? d_cnt[i] : 0;
    int incl = block_scan_incl(v, tid);
    if (tid == SCAN_T - 1) d_bsum[blockIdx.x] = incl;
}

__global__ void k_csr2() {
    int tid = threadIdx.x;
    int v = (tid < SCAN_B) ? d_bsum[tid] : 0;
    int lane = tid & 31, w = tid >> 5;
    int x = v;
    #pragma unroll
    for (int o = 1; o < 32; o <<= 1) {
        int y = __shfl_up_sync(0xffffffffu, x, o);
        if (lane >= o) x += y;
    }
    __shared__ int ws[8];
    if (lane == 31) ws[w] = x;
    __syncthreads();
    int off = 0;
    for (int j = 0; j < w; j++) off += ws[j];
    if (tid < SCAN_B) d_boff[tid] = x + off - v;
}

__global__ void k_csr3() {
    int tid = threadIdx.x;
    int i = blockIdx.x * SCAN_T + tid;
    int v = (i < NN) ? d_cnt[i] : 0;
    int incl = block_scan_incl(v, tid);
    int excl = incl - v + d_boff[blockIdx.x];
    if (i < NN) {
        d_rowptr[i] = excl;
        d_pos[i]    = excl;
        if (i == NN - 1) d_rowptr[NN] = excl + v;
    }
}

__global__ void k_scatter(const int* __restrict__ row, const int* __restrict__ col) {
    int i = blockIdx.x * blockDim.x + threadIdx.x;
    int stride = gridDim.x * blockDim.x;
    for (; i < NNZ / 4; i += stride) {
        int4 r = ((const int4*)row)[i];
        int4 c = ((const int4*)col)[i];
        int p;
        p = atomicAdd(&d_pos[r.x], 1); d_col[p] = c.x;
        p = atomicAdd(&d_pos[r.y], 1); d_col[p] = c.y;
        p = atomicAdd(&d_pos[r.z], 1); d_col[p] = c.z;
        p = atomicAdd(&d_pos[r.w], 1); d_col[p] = c.w;
    }
}

// ---- fp16 row gather helper: lane l owns 4 consecutive halves of a 64-col row
__device__ __forceinline__ float4 gather_row_h(const __half* base, int node, int l) {
    uint2 u = ((const uint2*)base)[(size_t)node * 16 + l];
    __half2 h0 = *(__half2*)&u.x;
    __half2 h1 = *(__half2*)&u.y;
    float2 f0 = __half22float2(h0);
    float2 f1 = __half22float2(h1);
    return make_float4(f0.x, f0.y, f1.x, f1.y);
}

__device__ __forceinline__ void store_row_h(__half* base, size_t idx, float4 s) {
    __half2 h0 = __floats2half2_rn(s.x, s.y);
    __half2 h1 = __floats2half2_rn(s.z, s.w);
    ((uint2*)base)[idx] = make_uint2(*(unsigned*)&h0, *(unsigned*)&h1);
}

// ---------------- layer 0: x'_0 = dinv * [rs^-0.5 * (sum embH[nbr] + embH[self]) * w]
// 16-lane groups, 2 rows per warp, 4 cols per lane; unconditional loads + mask
__global__ void k_rep0(const float* __restrict__ w) {
    int lane = threadIdx.x & 31;
    int l = lane & 15;
    int sbase = lane & 16;
    int gw = (blockIdx.x * blockDim.x + threadIdx.x) >> 4;
    if (gw >= NN) return;
    int beg = d_rowptr[gw], end = d_rowptr[gw + 1];
    int len = end - beg;
    int olen = __shfl_xor_sync(0xffffffffu, len, 16);
    int maxlen = max(len, olen);

    int self = NN + (gw >= N_USERS ? 1 : 0);
    float4 s = gather_row_h(d_embH, self, l);

    for (int r0 = 0; r0 < maxlen; r0 += 16) {
        int jj = beg + r0 + l;
        int c = 0; float m = 0.f;
        if (jj < end) { c = d_col[jj]; m = 1.f; }
        int kmax = min(16, maxlen - r0);
        #pragma unroll 4
        for (int k = 0; k < kmax; k++) {
            int   cc = __shfl_sync(0xffffffffu, c, sbase + k);
            float mm = __shfl_sync(0xffffffffu, m, sbase + k);
            float4 x = gather_row_h(d_embH, cc, l);
            s.x += mm * x.x; s.y += mm * x.y; s.z += mm * x.z; s.w += mm * x.w;
        }
    }
    float fv = rsqrtf((float)(len + 1));
    float dinv = (len > 0) ? rsqrtf((float)len) : 1.f;
    float4 w4 = ((const float4*)w)[l];
    float g = fv * dinv;
    s.x *= g * w4.x; s.y *= g * w4.y; s.z *= g * w4.z; s.w *= g * w4.w;
    store_row_h(d_X, (size_t)gw * 16 + l, s);
}

// ---------------- adj SpMM layer: x'_l = dinv^2 * sum x'_{l-1}[nbr] ----------
__global__ void k_spmm(int layer) {
    const __half* in  = d_X + (size_t)(layer - 1) * NN * EMB;
    __half*       out = d_X + (size_t)layer * NN * EMB;
    int lane = threadIdx.x & 31;
    int l = lane & 15;
    int sbase = lane & 16;
    int gw = (blockIdx.x * blockDim.x + threadIdx.x) >> 4;
    if (gw >= NN) return;
    int beg = d_rowptr[gw], end = d_rowptr[gw + 1];
    int len = end - beg;
    int olen = __shfl_xor_sync(0xffffffffu, len, 16);
    int maxlen = max(len, olen);

    float4 s = make_float4(0.f, 0.f, 0.f, 0.f);
    for (int r0 = 0; r0 < maxlen; r0 += 16) {
        int jj = beg + r0 + l;
        int c = 0; float m = 0.f;
        if (jj < end) { c = d_col[jj]; m = 1.f; }
        int kmax = min(16, maxlen - r0);
        #pragma unroll 4
        for (int k = 0; k < kmax; k++) {
            int   cc = __shfl_sync(0xffffffffu, c, sbase + k);
            float mm = __shfl_sync(0xffffffffu, m, sbase + k);
            float4 x = gather_row_h(in, cc, l);
            s.x += mm * x.x; s.y += mm * x.y; s.z += mm * x.z; s.w += mm * x.w;
        }
    }
    float di2 = (len > 0) ? (1.f / (float)len) : 1.f;   // dinv^2
    s.x *= di2; s.y *= di2; s.z *= di2; s.w *= di2;
    store_row_h(out, (size_t)gw * 16 + l, s);
}

// ---------------- combine: acc = 0.25 * sqrt(deg) * sum_l x'_l ---------------
__global__ void k_combine_items() {
    int t = blockIdx.x * blockDim.x + threadIdx.x;
    if (t >= N_ITEMS * 16) return;
    int it = t >> 4, l = t & 15;
    int node = N_USERS + it;
    float4 s = make_float4(0.f, 0.f, 0.f, 0.f);
    #pragma unroll
    for (int lay = 0; lay < 4; lay++) {
        float4 x = gather_row_h(d_X + (size_t)lay * NN * EMB, node, l);
        s.x += x.x; s.y += x.y; s.z += x.z; s.w += x.w;
    }
    int len = d_rowptr[node + 1] - d_rowptr[node];
    float m = ((len > 0) ? sqrtf((float)len) : 1.f) * 0.25f;
    s.x *= m; s.y *= m; s.z *= m; s.w *= m;
    store_row_h(d_Ih, (size_t)it * 16 + l, s);
}

__global__ void k_gatherU(const int* __restrict__ users) {
    int t = blockIdx.x * blockDim.x + threadIdx.x;
    if (t >= BATCH * 16) return;
    int b = t >> 4, l = t & 15;
    int node = users[b];
    float4 s = make_float4(0.f, 0.f, 0.f, 0.f);
    #pragma unroll
    for (int lay = 0; lay < 4; lay++) {
        float4 x = gather_row_h(d_X + (size_t)lay * NN * EMB, node, l);
        s.x += x.x; s.y += x.y; s.z += x.z; s.w += x.w;
    }
    int len = d_rowptr[node + 1] - d_rowptr[node];
    float m = ((len > 0) ? sqrtf((float)len) : 1.f) * 0.25f;
    s.x *= m; s.y *= m; s.z *= m; s.w *= m;
    store_row_h(d_Uh, (size_t)b * 16 + l, s);
}

// ---------------- tensor-core GEMM: out[512][150000] = Uh * Ih^T --------------
__device__ __forceinline__ unsigned smem_u32(const void* p) {
    return (unsigned)__cvta_generic_to_shared(p);
}

__global__ __launch_bounds__(256) void k_gemm_tc(float* __restrict__ out) {
    __shared__ __half Us[64][72];    // [m][k], pad 72 halves = 144B stride
    __shared__ __half Is[128][72];   // [n][k]
    int tid = threadIdx.x;
    int wid = tid >> 5, lane = tid & 31;
    int it0 = blockIdx.x * 128;
    int u0  = blockIdx.y * 64;

    for (int i = tid; i < 64 * 8; i += 256) {
        int r = i >> 3, c = i & 7;
        *(uint4*)&Us[r][c * 8] = ((const uint4*)d_Uh)[(u0 + r) * 8 + c];
    }
    for (int i = tid; i < 128 * 8; i += 256) {
        int r = i >> 3, c = i & 7;
        int git = it0 + r;
        uint4 v = make_uint4(0u, 0u, 0u, 0u);
        if (git < N_ITEMS) v = ((const uint4*)d_Ih)[(size_t)git * 8 + c];
        *(uint4*)&Is[r][c * 8] = v;
    }
    __syncthreads();

    int wm = (wid & 3) * 16;
    int wn = (wid >> 2) * 64;

    float acc[8][4];
    #pragma unroll
    for (int n = 0; n < 8; n++)
        #pragma unroll
        for (int j = 0; j < 4; j++) acc[n][j] = 0.f;

    #pragma unroll
    for (int ks = 0; ks < 4; ks++) {
        int k0 = ks * 16;
        unsigned a0, a1, a2, a3;
        {
            const __half* ap = (lane < 16) ? &Us[wm + lane][k0]
                                           : &Us[wm + lane - 16][k0 + 8];
            unsigned addr = smem_u32(ap);
            asm volatile("ldmatrix.sync.aligned.m8n8.x4.shared.b16 {%0,%1,%2,%3}, [%4];"
                         : "=r"(a0), "=r"(a1), "=r"(a2), "=r"(a3) : "r"(addr));
        }
        #pragma unroll
        for (int nt = 0; nt < 8; nt += 2) {
            unsigned b0, b1, b2, b3;
            int sub = lane >> 3;
            int rr  = wn + nt * 8 + (lane & 7) + ((sub >> 1) * 8);
            int kk  = k0 + (sub & 1) * 8;
            unsigned addr = smem_u32(&Is[rr][kk]);
            asm volatile("ldmatrix.sync.aligned.m8n8.x4.shared.b16 {%0,%1,%2,%3}, [%4];"
                         : "=r"(b0), "=r"(b1), "=r"(b2), "=r"(b3) : "r"(addr));
            asm volatile("mma.sync.aligned.m16n8k16.row.col.f32.f16.f16.f32 "
                         "{%0,%1,%2,%3}, {%4,%5,%6,%7}, {%8,%9}, {%0,%1,%2,%3};"
                         : "+f"(acc[nt][0]), "+f"(acc[nt][1]), "+f"(acc[nt][2]), "+f"(acc[nt][3])
                         : "r"(a0), "r"(a1), "r"(a2), "r"(a3), "r"(b0), "r"(b1));
            asm volatile("mma.sync.aligned.m16n8k16.row.col.f32.f16.f16.f32 "
                         "{%0,%1,%2,%3}, {%4,%5,%6,%7}, {%8,%9}, {%0,%1,%2,%3};"
                         : "+f"(acc[nt+1][0]), "+f"(acc[nt+1][1]), "+f"(acc[nt+1][2]), "+f"(acc[nt+1][3])
                         : "r"(a0), "r"(a1), "r"(a2), "r"(a3), "r"(b2), "r"(b3));
        }
    }

    int m0 = u0 + wm + (lane >> 2);
    int cbase = it0 + wn + (lane & 3) * 2;
    #pragma unroll
    for (int nt = 0; nt < 8; nt++) {
        int col = cbase + nt * 8;
        if (col < N_ITEMS) {
            *(float2*)&out[(size_t)m0 * N_ITEMS + col]       = make_float2(acc[nt][0], acc[nt][1]);
            *(float2*)&out[(size_t)(m0 + 8) * N_ITEMS + col] = make_float2(acc[nt][2], acc[nt][3]);
        }
    }
}

// ---------------- launch -----------------------------------------------------
extern "C" void kernel_launch(void* const* d_in, const int* in_sizes, int n_in,
                              void* d_out, int out_size) {
    const int*   users = (const int*)  d_in[0];
    const float* emb   = (const float*)d_in[1];
    const float* w     = (const float*)d_in[2];
    const int*   arow  = (const int*)  d_in[3];
    const int*   acol  = (const int*)  d_in[4];
    float* out = (float*)d_out;

    void* cntp = nullptr;
    cudaGetSymbolAddress(&cntp, d_cnt);
    cudaMemsetAsync(cntp, 0, NN * sizeof(int));

    k_cvt_emb<<<(NFEAT * EMB / 4 + 255) / 256, 256>>>(emb);
    k_hist<<<2048, 256>>>(arow);
    k_csr1<<<SCAN_B, SCAN_T>>>();
    k_csr2<<<1, 256>>>();
    k_csr3<<<SCAN_B, SCAN_T>>>();
    k_scatter<<<2048, 256>>>(arow, acol);

    int blocks = (NN * 16 + 255) / 256;    // 16 lanes per row
    k_rep0<<<blocks, 256>>>(w);
    k_spmm<<<blocks, 256>>>(1);
    k_spmm<<<blocks, 256>>>(2);
    k_spmm<<<blocks, 256>>>(3);

    k_combine_items<<<(N_ITEMS * 16 + 255) / 256, 256>>>();
    k_gatherU<<<(BATCH * 16 + 255) / 256, 256>>>(users);

    dim3 g((N_ITEMS + 127) / 128, BATCH / 64);
    k_gemm_tc<<<g, 256>>>(out);
}

// round 7
// speedup vs baseline: 1.4370x; 1.0195x over previous
#include <cuda_runtime.h>
#include <cuda_bf16.h>
#include <cuda_fp16.h>

#define N_USERS 100000
#define N_ITEMS 150000
#define NN      250000
#define NFEAT   250002
#define NNZ     4000000
#define NNZ_H   2000000
#define EMB     64
#define BATCH   512

#define SCAN_T  1024
#define SCAN_B  ((NN + SCAN_T - 1) / SCAN_T)   // 245

// ---------------- scratch (device globals; no runtime allocation) ------------
__device__ int    d_cnt[NN];
__device__ int    d_rowptr[NN + 1];
__device__ int    d_pos[NN];
__device__ int    d_col[NNZ];
__device__ int    d_bsum[SCAN_B];
__device__ int    d_boff[SCAN_B];
__device__ __half d_embH[(size_t)NFEAT * EMB];
__device__ __half d_X[(size_t)3 * NN * EMB];    // pre-scaled reps x'_0..x'_2
__device__ __half d_Uh[BATCH * EMB];
__device__ __half d_Ih[(size_t)N_ITEMS * EMB];

// ---------------- emb -> fp16 ------------------------------------------------
__global__ void k_cvt_emb(const float* __restrict__ emb) {
    int i = blockIdx.x * blockDim.x + threadIdx.x;            // float4 index
    const int total = (NFEAT * EMB) / 4;
    if (i < total) {
        float4 f = ((const float4*)emb)[i];
        __half2 h0 = __floats2half2_rn(f.x, f.y);
        __half2 h1 = __floats2half2_rn(f.z, f.w);
        ((uint2*)d_embH)[i] = make_uint2(*(unsigned*)&h0, *(unsigned*)&h1);
    }
}

// ---------------- CSR build (mirror-compressed: read first 2M pairs) ---------
__global__ void k_hist(const int* __restrict__ row, const int* __restrict__ col) {
    int i = blockIdx.x * blockDim.x + threadIdx.x;
    int stride = gridDim.x * blockDim.x;
    for (; i < NNZ_H / 4; i += stride) {
        int4 r = ((const int4*)row)[i];
        int4 c = ((const int4*)col)[i];
        atomicAdd(&d_cnt[r.x], 1); atomicAdd(&d_cnt[c.x], 1);
        atomicAdd(&d_cnt[r.y], 1); atomicAdd(&d_cnt[c.y], 1);
        atomicAdd(&d_cnt[r.z], 1); atomicAdd(&d_cnt[c.z], 1);
        atomicAdd(&d_cnt[r.w], 1); atomicAdd(&d_cnt[c.w], 1);
    }
}

__device__ __forceinline__ int block_scan_incl(int v, int tid) {
    int lane = tid & 31, w = tid >> 5;
    int x = v;
    #pragma unroll
    for (int o = 1; o < 32; o <<= 1) {
        int y = __shfl_up_sync(0xffffffffu, x, o);
        if (lane >= o) x += y;
    }
    __shared__ int ws[32];
    if (lane == 31) ws[w] = x;
    __syncthreads();
    if (w == 0) {
        int y = ws[lane];
        #pragma unroll
        for (int o = 1; o < 32; o <<= 1) {
            int z = __shfl_up_sync(0xffffffffu, y, o);
            if (lane >= o) y += z;
        }
        ws[lane] = y;
    }
    __syncthreads();
    return x + (w > 0 ? ws[w - 1] : 0);
}

__global__ void k_csr1() {
    int tid = threadIdx.x;
    int i = blockIdx.x * SCAN_T + tid;
    int v = (i < NN) ? d_cnt[i] : 0;
    int incl = block_scan_incl(v, tid);
    if (tid == SCAN_T - 1) d_bsum[blockIdx.x] = incl;
}

__global__ void k_csr2() {
    int tid = threadIdx.x;
    int v = (tid < SCAN_B) ? d_bsum[tid] : 0;
    int lane = tid & 31, w = tid >> 5;
    int x = v;
    #pragma unroll
    for (int o = 1; o < 32; o <<= 1) {
        int y = __shfl_up_sync(0xffffffffu, x, o);
        if (lane >= o) x += y;
    }
    __shared__ int ws[8];
    if (lane == 31) ws[w] = x;
    __syncthreads();
    int off = 0;
    for (int j = 0; j < w; j++) off += ws[j];
    if (tid < SCAN_B) d_boff[tid] = x + off - v;
}

__global__ void k_csr3() {
    int tid = threadIdx.x;
    int i = blockIdx.x * SCAN_T + tid;
    int v = (i < NN) ? d_cnt[i] : 0;
    int incl = block_scan_incl(v, tid);
    int excl = incl - v + d_boff[blockIdx.x];
    if (i < NN) {
        d_rowptr[i] = excl;
        d_pos[i]    = excl;
        if (i == NN - 1) d_rowptr[NN] = excl + v;
    }
}

__global__ void k_scatter(const int* __restrict__ row, const int* __restrict__ col) {
    int i = blockIdx.x * blockDim.x + threadIdx.x;
    int stride = gridDim.x * blockDim.x;
    for (; i < NNZ_H / 4; i += stride) {
        int4 r = ((const int4*)row)[i];
        int4 c = ((const int4*)col)[i];
        int p;
        p = atomicAdd(&d_pos[r.x], 1); d_col[p] = c.x;
        p = atomicAdd(&d_pos[c.x], 1); d_col[p] = r.x;
        p = atomicAdd(&d_pos[r.y], 1); d_col[p] = c.y;
        p = atomicAdd(&d_pos[c.y], 1); d_col[p] = r.y;
        p = atomicAdd(&d_pos[r.z], 1); d_col[p] = c.z;
        p = atomicAdd(&d_pos[c.z], 1); d_col[p] = r.z;
        p = atomicAdd(&d_pos[r.w], 1); d_col[p] = c.w;
        p = atomicAdd(&d_pos[c.w], 1); d_col[p] = r.w;
    }
}

// ---- fp16 row gather helper: lane l owns 4 consecutive halves of a 64-col row
__device__ __forceinline__ float4 gather_row_h(const __half* base, int node, int l) {
    uint2 u = ((const uint2*)base)[(size_t)node * 16 + l];
    __half2 h0 = *(__half2*)&u.x;
    __half2 h1 = *(__half2*)&u.y;
    float2 f0 = __half22float2(h0);
    float2 f1 = __half22float2(h1);
    return make_float4(f0.x, f0.y, f1.x, f1.y);
}

__device__ __forceinline__ void store_row_h(__half* base, size_t idx, float4 s) {
    __half2 h0 = __floats2half2_rn(s.x, s.y);
    __half2 h1 = __floats2half2_rn(s.z, s.w);
    ((uint2*)base)[idx] = make_uint2(*(unsigned*)&h0, *(unsigned*)&h1);
}

// ---- shared gather loop: sum over neighbors of row `gw` from `in` -----------
__device__ __forceinline__ float4 nbr_sum(const __half* in, int beg, int end,
                                          int len, int sbase, int l) {
    int olen = __shfl_xor_sync(0xffffffffu, len, 16);
    int maxlen = max(len, olen);
    float4 s = make_float4(0.f, 0.f, 0.f, 0.f);
    for (int r0 = 0; r0 < maxlen; r0 += 16) {
        int jj = beg + r0 + l;
        int c = 0; float m = 0.f;
        if (jj < end) { c = d_col[jj]; m = 1.f; }
        int kmax = min(16, maxlen - r0);
        #pragma unroll 4
        for (int k = 0; k < kmax; k++) {
            int   cc = __shfl_sync(0xffffffffu, c, sbase + k);
            float mm = __shfl_sync(0xffffffffu, m, sbase + k);
            float4 x = gather_row_h(in, cc, l);
            s.x += mm * x.x; s.y += mm * x.y; s.z += mm * x.z; s.w += mm * x.w;
        }
    }
    return s;
}

// ---------------- layer 0: x'_0 = dinv * [rs^-0.5 * (sum embH[nbr] + embH[self]) * w]
__global__ void k_rep0(const float* __restrict__ w) {
    int lane = threadIdx.x & 31;
    int l = lane & 15;
    int sbase = lane & 16;
    int gw = (blockIdx.x * blockDim.x + threadIdx.x) >> 4;
    if (gw >= NN) return;
    int beg = d_rowptr[gw], end = d_rowptr[gw + 1];
    int len = end - beg;

    int self = NN + (gw >= N_USERS ? 1 : 0);
    float4 sf = gather_row_h(d_embH, self, l);
    float4 s = nbr_sum(d_embH, beg, end, len, sbase, l);
    s.x += sf.x; s.y += sf.y; s.z += sf.z; s.w += sf.w;

    float fv = rsqrtf((float)(len + 1));
    float dinv = (len > 0) ? rsqrtf((float)len) : 1.f;
    float4 w4 = ((const float4*)w)[l];
    float g = fv * dinv;
    s.x *= g * w4.x; s.y *= g * w4.y; s.z *= g * w4.z; s.w *= g * w4.w;
    store_row_h(d_X, (size_t)gw * 16 + l, s);
}

// ---------------- adj SpMM layer (all nodes): x'_l = dinv^2 * sum x'_{l-1}[nbr]
__global__ void k_spmm(int layer) {
    const __half* in  = d_X + (size_t)(layer - 1) * NN * EMB;
    __half*       out = d_X + (size_t)layer * NN * EMB;
    int lane = threadIdx.x & 31;
    int l = lane & 15;
    int sbase = lane & 16;
    int gw = (blockIdx.x * blockDim.x + threadIdx.x) >> 4;
    if (gw >= NN) return;
    int beg = d_rowptr[gw], end = d_rowptr[gw + 1];
    int len = end - beg;

    float4 s = nbr_sum(in, beg, end, len, sbase, l);
    float di2 = (len > 0) ? (1.f / (float)len) : 1.f;
    s.x *= di2; s.y *= di2; s.z *= di2; s.w *= di2;
    store_row_h(out, (size_t)gw * 16 + l, s);
}

// ---------------- layer 3 (items only) + combine -> d_Ih ----------------------
// x3 = dinv^2 * sum x2[nbr]; Ih = 0.25*sqrt(deg)*(x0+x1+x2+x3)
__global__ void k_spmm_item() {
    const __half* in = d_X + (size_t)2 * NN * EMB;
    int lane = threadIdx.x & 31;
    int l = lane & 15;
    int sbase = lane & 16;
    int it = (blockIdx.x * blockDim.x + threadIdx.x) >> 4;
    if (it >= N_ITEMS) return;
    int node = N_USERS + it;
    int beg = d_rowptr[node], end = d_rowptr[node + 1];
    int len = end - beg;

    float4 s = nbr_sum(in, beg, end, len, sbase, l);
    float di2 = (len > 0) ? (1.f / (float)len) : 1.f;
    s.x *= di2; s.y *= di2; s.z *= di2; s.w *= di2;

    #pragma unroll
    for (int lay = 0; lay < 3; lay++) {
        float4 x = gather_row_h(d_X + (size_t)lay * NN * EMB, node, l);
        s.x += x.x; s.y += x.y; s.z += x.z; s.w += x.w;
    }
    float m = ((len > 0) ? sqrtf((float)len) : 1.f) * 0.25f;
    s.x *= m; s.y *= m; s.z *= m; s.w *= m;
    store_row_h(d_Ih, (size_t)it * 16 + l, s);
}

// ---------------- layer 3 (batch users only) + combine -> d_Uh ----------------
__global__ void k_finalU(const int* __restrict__ users) {
    const __half* in = d_X + (size_t)2 * NN * EMB;
    int lane = threadIdx.x & 31;
    int l = lane & 15;
    int sbase = lane & 16;
    int b = (blockIdx.x * blockDim.x + threadIdx.x) >> 4;
    if (b >= BATCH) return;
    int node = users[b];
    int beg = d_rowptr[node], end = d_rowptr[node + 1];
    int len = end - beg;

    float4 s = nbr_sum(in, beg, end, len, sbase, l);
    float di2 = (len > 0) ? (1.f / (float)len) : 1.f;
    s.x *= di2; s.y *= di2; s.z *= di2; s.w *= di2;

    #pragma unroll
    for (int lay = 0; lay < 3; lay++) {
        float4 x = gather_row_h(d_X + (size_t)lay * NN * EMB, node, l);
        s.x += x.x; s.y += x.y; s.z += x.z; s.w += x.w;
    }
    float m = ((len > 0) ? sqrtf((float)len) : 1.f) * 0.25f;
    s.x *= m; s.y *= m; s.z *= m; s.w *= m;
    store_row_h(d_Uh, (size_t)b * 16 + l, s);
}

// ---------------- tensor-core GEMM: out[512][150000] = Uh * Ih^T --------------
// block: 256 thr (8 warps), tile 128 users x 128 items, K=64
// warp tile: 32m x 64n
__device__ __forceinline__ unsigned smem_u32(const void* p) {
    return (unsigned)__cvta_generic_to_shared(p);
}

__global__ __launch_bounds__(256) void k_gemm_tc(float* __restrict__ out) {
    __shared__ __half Us[128][72];   // [m][k]
    __shared__ __half Is[128][72];   // [n][k]
    int tid = threadIdx.x;
    int wid = tid >> 5, lane = tid & 31;
    int it0 = blockIdx.x * 128;
    int u0  = blockIdx.y * 128;

    for (int i = tid; i < 128 * 8; i += 256) {
        int r = i >> 3, c = i & 7;
        *(uint4*)&Us[r][c * 8] = ((const uint4*)d_Uh)[(u0 + r) * 8 + c];
    }
    for (int i = tid; i < 128 * 8; i += 256) {
        int r = i >> 3, c = i & 7;
        int git = it0 + r;
        uint4 v = make_uint4(0u, 0u, 0u, 0u);
        if (git < N_ITEMS) v = ((const uint4*)d_Ih)[(size_t)git * 8 + c];
        *(uint4*)&Is[r][c * 8] = v;
    }
    __syncthreads();

    int wm = (wid & 3) * 32;
    int wn = (wid >> 2) * 64;

    float acc[2][8][4];
    #pragma unroll
    for (int mf = 0; mf < 2; mf++)
        #pragma unroll
        for (int n = 0; n < 8; n++)
            #pragma unroll
            for (int j = 0; j < 4; j++) acc[mf][n][j] = 0.f;

    #pragma unroll
    for (int ks = 0; ks < 4; ks++) {
        int k0 = ks * 16;
        unsigned a[2][4];
        #pragma unroll
        for (int mf = 0; mf < 2; mf++) {
            int rr = wm + mf * 16 + (lane & 15);
            int kk = k0 + (lane >> 4) * 8;
            unsigned addr = smem_u32(&Us[rr][kk]);
            asm volatile("ldmatrix.sync.aligned.m8n8.x4.shared.b16 {%0,%1,%2,%3}, [%4];"
                         : "=r"(a[mf][0]), "=r"(a[mf][1]), "=r"(a[mf][2]), "=r"(a[mf][3])
                         : "r"(addr));
        }
        #pragma unroll
        for (int nt = 0; nt < 8; nt += 2) {
            unsigned b0, b1, b2, b3;
            int sub = lane >> 3;
            int rr  = wn + nt * 8 + (lane & 7) + ((sub >> 1) * 8);
            int kk  = k0 + (sub & 1) * 8;
            unsigned addr = smem_u32(&Is[rr][kk]);
            asm volatile("ldmatrix.sync.aligned.m8n8.x4.shared.b16 {%0,%1,%2,%3}, [%4];"
                         : "=r"(b0), "=r"(b1), "=r"(b2), "=r"(b3) : "r"(addr));
            #pragma unroll
            for (int mf = 0; mf < 2; mf++) {
                asm volatile("mma.sync.aligned.m16n8k16.row.col.f32.f16.f16.f32 "
                             "{%0,%1,%2,%3}, {%4,%5,%6,%7}, {%8,%9}, {%0,%1,%2,%3};"
                             : "+f"(acc[mf][nt][0]), "+f"(acc[mf][nt][1]),
                               "+f"(acc[mf][nt][2]), "+f"(acc[mf][nt][3])
                             : "r"(a[mf][0]), "r"(a[mf][1]), "r"(a[mf][2]), "r"(a[mf][3]),
                               "r"(b0), "r"(b1));
                asm volatile("mma.sync.aligned.m16n8k16.row.col.f32.f16.f16.f32 "
                             "{%0,%1,%2,%3}, {%4,%5,%6,%7}, {%8,%9}, {%0,%1,%2,%3};"
                             : "+f"(acc[mf][nt+1][0]), "+f"(acc[mf][nt+1][1]),
                               "+f"(acc[mf][nt+1][2]), "+f"(acc[mf][nt+1][3])
                             : "r"(a[mf][0]), "r"(a[mf][1]), "r"(a[mf][2]), "r"(a[mf][3]),
                               "r"(b2), "r"(b3));
            }
        }
    }

    int cbase = it0 + wn + (lane & 3) * 2;
    #pragma unroll
    for (int mf = 0; mf < 2; mf++) {
        int m0 = u0 + wm + mf * 16 + (lane >> 2);
        #pragma unroll
        for (int nt = 0; nt < 8; nt++) {
            int col = cbase + nt * 8;
            if (col < N_ITEMS) {
                *(float2*)&out[(size_t)m0 * N_ITEMS + col] =
                    make_float2(acc[mf][nt][0], acc[mf][nt][1]);
                *(float2*)&out[(size_t)(m0 + 8) * N_ITEMS + col] =
                    make_float2(acc[mf][nt][2], acc[mf][nt][3]);
            }
        }
    }
}

// ---------------- launch -----------------------------------------------------
extern "C" void kernel_launch(void* const* d_in, const int* in_sizes, int n_in,
                              void* d_out, int out_size) {
    const int*   users = (const int*)  d_in[0];
    const float* emb   = (const float*)d_in[1];
    const float* w     = (const float*)d_in[2];
    const int*   arow  = (const int*)  d_in[3];
    const int*   acol  = (const int*)  d_in[4];
    float* out = (float*)d_out;

    void* cntp = nullptr;
    cudaGetSymbolAddress(&cntp, d_cnt);
    cudaMemsetAsync(cntp, 0, NN * sizeof(int));

    k_cvt_emb<<<(NFEAT * EMB / 4 + 255) / 256, 256>>>(emb);
    k_hist<<<2048, 256>>>(arow, acol);
    k_csr1<<<SCAN_B, SCAN_T>>>();
    k_csr2<<<1, 256>>>();
    k_csr3<<<SCAN_B, SCAN_T>>>();
    k_scatter<<<2048, 256>>>(arow, acol);

    int blocks = (NN * 16 + 255) / 256;    // 16 lanes per row
    k_rep0<<<blocks, 256>>>(w);
    k_spmm<<<blocks, 256>>>(1);
    k_spmm<<<blocks, 256>>>(2);
    k_spmm_item<<<(N_ITEMS * 16 + 255) / 256, 256>>>();
    k_finalU<<<(BATCH * 16 + 255) / 256, 256>>>(users);

    dim3 g((N_ITEMS + 127) / 128, BATCH / 128);
    k_gemm_tc<<<g, 256>>>(out);
}